// round 12
// baseline (speedup 1.0000x reference)
#include <cuda_runtime.h>
#include <cuda_fp16.h>
#include <cstdint>
#include <math.h>

// Problem constants
#define NT 1024
#define NA 2
#define NE 8
#define NI 2816
#define ND 1024
#define NSLOT (NT * NA)

// GEMM tiling: block 128x128x32, 512 threads (16 warps: 4M x 4N), 3-stage pipe
#define BM 128
#define BN 128
#define BK 32
#define LDS_STRIDE 80              // bytes per smem tile row (32*2 padded to 80)
#define TB (128 * LDS_STRIDE)      // one tile: 128 rows x 80B = 10240 B

// ---------------------------------------------------------------------------
// Device global scratch
// ---------------------------------------------------------------------------
__device__ int g_count[NE];
__device__ int g_slots[NE][NSLOT];
__device__ int g_is64;

__device__ __align__(16) __half g_x16[NT * ND];
__device__ __align__(16) __half g_h16[(size_t)NSLOT * NI];

// ---------------------------------------------------------------------------
// PTX helpers (base-target sm_103 features only)
// ---------------------------------------------------------------------------
__device__ __forceinline__ uint32_t smem_u32(const void* p) {
    uint32_t a;
    asm("{ .reg .u64 t; cvta.to.shared.u64 t, %1; cvt.u32.u64 %0, t; }"
        : "=r"(a) : "l"(p));
    return a;
}

#define LDSM4(R, addr) \
    asm volatile("ldmatrix.sync.aligned.m8n8.x4.shared.b16 {%0,%1,%2,%3}, [%4];" \
        : "=r"((R)[0]), "=r"((R)[1]), "=r"((R)[2]), "=r"((R)[3]) : "r"(addr))

#define MMA_F16(C, A, B0, B1) \
    asm volatile("mma.sync.aligned.m16n8k16.row.col.f32.f16.f16.f32 " \
        "{%0,%1,%2,%3}, {%4,%5,%6,%7}, {%8,%9}, {%0,%1,%2,%3};" \
        : "+f"((C)[0]), "+f"((C)[1]), "+f"((C)[2]), "+f"((C)[3]) \
        : "r"((A)[0]), "r"((A)[1]), "r"((A)[2]), "r"((A)[3]), "r"(B0), "r"(B1))

#define CP_ASYNC16(dst, src) \
    asm volatile("cp.async.cg.shared.global [%0], [%1], 16;" :: "r"(dst), "l"(src))
#define CP_COMMIT() asm volatile("cp.async.commit_group;" ::: "memory")
#define CP_WAIT(N) asm volatile("cp.async.wait_group %0;" :: "n"(N) : "memory")

__device__ __forceinline__ uint32_t pack2h(float a, float b) {
    __half2 h = __floats2half2_rn(a, b);
    return *reinterpret_cast<uint32_t*>(&h);
}
// 8 fp32 -> 8 packed fp16 (uint4)
__device__ __forceinline__ uint4 pack8h(const float4& a, const float4& b) {
    uint4 r;
    r.x = pack2h(a.x, a.y);
    r.y = pack2h(a.z, a.w);
    r.z = pack2h(b.x, b.y);
    r.w = pack2h(b.z, b.w);
    return r;
}

// ---------------------------------------------------------------------------
// Routing
// ---------------------------------------------------------------------------
__global__ void detect_and_zero_kernel(const int* __restrict__ idx32) {
    __shared__ int any;
    if (threadIdx.x == 0) any = 0;
    if (threadIdx.x < NE) g_count[threadIdx.x] = 0;
    __syncthreads();
    int local = 0;
    for (int i = threadIdx.x; i < NSLOT / 2; i += blockDim.x)
        local |= idx32[2 * i + 1];
    if (local) atomicOr(&any, 1);
    __syncthreads();
    if (threadIdx.x == 0) g_is64 = (any == 0) ? 1 : 0;
}

__global__ void route_kernel(const int* __restrict__ idx32) {
    int s = blockIdx.x * blockDim.x + threadIdx.x;
    if (s < NSLOT) {
        int e = g_is64 ? idx32[2 * s] : idx32[s];
        e &= (NE - 1);
        int p = atomicAdd(&g_count[e], 1);
        g_slots[e][p] = s;
    }
}

// ---------------------------------------------------------------------------
// x: fp32 -> fp16 (tiny)
// ---------------------------------------------------------------------------
__global__ __launch_bounds__(256) void conv_f16_kernel(
    const float* __restrict__ src, __half* __restrict__ dst, int n8)
{
    int i = blockIdx.x * blockDim.x + threadIdx.x;
    if (i >= n8) return;
    float4 a = reinterpret_cast<const float4*>(src)[2 * i];
    float4 b = reinterpret_cast<const float4*>(src)[2 * i + 1];
    reinterpret_cast<uint4*>(dst)[i] = pack8h(a, b);
}

// ---------------------------------------------------------------------------
// GEMM1: h = silu(X @ w1[e]^T) * (X @ w3[e]^T). Pure fp16, fp32 acc.
// 3-stage pipeline, ONE barrier per chunk; inner chunk is software-pipelined
// over 4 sections (kb x nb2) with register double-buffered LDSM.
// Stage tiles: A, B1, B3 (each 128 x 32 fp16, 80B stride)
// ---------------------------------------------------------------------------
#define STAGE1B (3 * TB)                    // 30720
#define SMEM1_BYTES (1024 + 3 * STAGE1B)    // 93184

__global__ __launch_bounds__(512, 1) void gemm1_tc(
    const float* __restrict__ w1, const float* __restrict__ w3)
{
    const int e = blockIdx.z;
    const int ne = g_count[e];
    const int mBase = blockIdx.y * BM;
    if (mBase >= ne) return;
    const int nBase = blockIdx.x * BN;

    extern __shared__ char smem[];
    const uint32_t sb = smem_u32(smem);
    const int tid = threadIdx.x;
    const int wid = tid >> 5;
    const int lane = tid & 31;

    int* sSlot = reinterpret_cast<int*>(smem);
    if (tid < BM) {
        int m = mBase + tid;
        sSlot[tid] = (m < ne) ? g_slots[e][m] : -1;
    }
    __syncthreads();

    // --- A producer: one 16B granule per thread ---
    const int prow = tid >> 2;
    const int pcolg = tid & 3;
    const uint32_t adoff = 1024u + (uint32_t)prow * LDS_STRIDE + pcolg * 16;
    const __half* asrcp;
    {
        int s = sSlot[prow];
        int tok = (s >= 0 ? s : 0) >> 1;
        asrcp = g_x16 + (size_t)tok * ND + pcolg * 8;
    }

    // --- W producer: 16 fp32 -> 16 fp16 per thread per chunk (w1 or w3) ---
    const int wt    = tid >> 8;            // 0: w1, 1: w3
    const int wrow  = (tid & 255) >> 1;    // 0..127
    const int whalf = tid & 1;             // 16 floats each
    const float* wsrc = (wt == 0 ? w1 : w3)
        + (size_t)e * NI * ND + (size_t)(nBase + wrow) * ND + whalf * 16;
    const uint32_t wdoff = (uint32_t)wrow * LDS_STRIDE + whalf * 32;
    const uint32_t wtoff = (uint32_t)(1 + wt) * TB;   // B1 or B3 within stage

    // --- consumer: 16 warps = 4M x 4N, warp tile 32x32 ---
    const int warpM = wid & 3;
    const int warpN = wid >> 2;
    const uint32_t aoff = (uint32_t)(warpM * 32 + (lane & 15)) * LDS_STRIDE
                        + (uint32_t)(lane >> 4) * 16;
    const uint32_t boff = (uint32_t)(warpN * 32 + (lane & 7) + ((lane >> 3) & 2) * 4) * LDS_STRIDE
                        + (uint32_t)((lane >> 3) & 1) * 16;

    float acc1[2][4][4] = {};
    float acc3[2][4][4] = {};

    const int NCH = ND / BK;   // 32

    // --- prologue: cp A for chunks 0,1 (stages 0,1); convert+store W chunk 0 ---
    CP_ASYNC16(adoff + sb, asrcp);
    CP_COMMIT();
    CP_ASYNC16(adoff + sb + STAGE1B, asrcp + BK);
    CP_COMMIT();
    {
        float4 s0 = *reinterpret_cast<const float4*>(wsrc + 0);
        float4 s1 = *reinterpret_cast<const float4*>(wsrc + 4);
        float4 s2 = *reinterpret_cast<const float4*>(wsrc + 8);
        float4 s3 = *reinterpret_cast<const float4*>(wsrc + 12);
        *reinterpret_cast<uint4*>(smem + 1024u + wtoff + wdoff)      = pack8h(s0, s1);
        *reinterpret_cast<uint4*>(smem + 1024u + wtoff + wdoff + 16) = pack8h(s2, s3);
    }

    uint32_t stgRd = 0, stgW = STAGE1B, stgCp = 2 * STAGE1B;

    for (int c = 0; c < NCH; c++) {
        const bool haveCp = (c + 2 < NCH);
        const bool haveW  = (c + 1 < NCH);
        const int kt = (c + 1) * BK;

        if (c + 1 < NCH) { CP_WAIT(1); } else { CP_WAIT(0); }
        __syncthreads();
        if (haveCp) {
            const int kt2 = (c + 2) * BK;
            CP_ASYNC16(adoff + sb + stgCp, asrcp + kt2);
            CP_COMMIT();
        }

        const uint32_t bb = sb + 1024u + stgRd;
        const uint32_t tA = bb;
        const uint32_t tB1 = bb + TB, tB3 = bb + 2 * TB;
        const uint32_t NO = 16 * LDS_STRIDE;

        // W half0 LDG (consumed after section 1)
        float4 s0, s1;
        if (haveW) {
            s0 = *reinterpret_cast<const float4*>(wsrc + kt + 0);
            s1 = *reinterpret_cast<const float4*>(wsrc + kt + 4);
        }

        // preload section 0 (kb0, nb0)
        uint32_t aCur[2][4], aNxt[2][4], b1A[4], b3A[4], b1B[4], b3B[4];
        LDSM4(aCur[0], tA + aoff);
        LDSM4(aCur[1], tA + aoff + NO);
        LDSM4(b1A, tB1 + boff);
        LDSM4(b3A, tB3 + boff);

        // --- section 0 (kb0, nb0): prefetch B(nb1, kb0) ---
        LDSM4(b1B, tB1 + boff + NO);
        LDSM4(b3B, tB3 + boff + NO);
        MMA_F16(acc1[0][0], aCur[0], b1A[0], b1A[1]);
        MMA_F16(acc1[0][1], aCur[0], b1A[2], b1A[3]);
        MMA_F16(acc1[1][0], aCur[1], b1A[0], b1A[1]);
        MMA_F16(acc1[1][1], aCur[1], b1A[2], b1A[3]);
        MMA_F16(acc3[0][0], aCur[0], b3A[0], b3A[1]);
        MMA_F16(acc3[0][1], aCur[0], b3A[2], b3A[3]);
        MMA_F16(acc3[1][0], aCur[1], b3A[0], b3A[1]);
        MMA_F16(acc3[1][1], aCur[1], b3A[2], b3A[3]);

        // --- section 1 (kb0, nb1): prefetch A(kb1) + B(nb0, kb1) ---
        LDSM4(aNxt[0], tA + aoff + 32);
        LDSM4(aNxt[1], tA + aoff + NO + 32);
        LDSM4(b1A, tB1 + boff + 32);
        LDSM4(b3A, tB3 + boff + 32);
        MMA_F16(acc1[0][2], aCur[0], b1B[0], b1B[1]);
        MMA_F16(acc1[0][3], aCur[0], b1B[2], b1B[3]);
        MMA_F16(acc1[1][2], aCur[1], b1B[0], b1B[1]);
        MMA_F16(acc1[1][3], aCur[1], b1B[2], b1B[3]);
        MMA_F16(acc3[0][2], aCur[0], b3B[0], b3B[1]);
        MMA_F16(acc3[0][3], aCur[0], b3B[2], b3B[3]);
        MMA_F16(acc3[1][2], aCur[1], b3B[0], b3B[1]);
        MMA_F16(acc3[1][3], aCur[1], b3B[2], b3B[3]);

        // W half0 STS; W half1 LDG
        if (haveW) {
            *reinterpret_cast<uint4*>(smem + 1024u + stgW + wtoff + wdoff) = pack8h(s0, s1);
            s0 = *reinterpret_cast<const float4*>(wsrc + kt + 8);
            s1 = *reinterpret_cast<const float4*>(wsrc + kt + 12);
        }

        // --- section 2 (kb1, nb0): prefetch B(nb1, kb1) ---
        LDSM4(b1B, tB1 + boff + NO + 32);
        LDSM4(b3B, tB3 + boff + NO + 32);
        MMA_F16(acc1[0][0], aNxt[0], b1A[0], b1A[1]);
        MMA_F16(acc1[0][1], aNxt[0], b1A[2], b1A[3]);
        MMA_F16(acc1[1][0], aNxt[1], b1A[0], b1A[1]);
        MMA_F16(acc1[1][1], aNxt[1], b1A[2], b1A[3]);
        MMA_F16(acc3[0][0], aNxt[0], b3A[0], b3A[1]);
        MMA_F16(acc3[0][1], aNxt[0], b3A[2], b3A[3]);
        MMA_F16(acc3[1][0], aNxt[1], b3A[0], b3A[1]);
        MMA_F16(acc3[1][1], aNxt[1], b3A[2], b3A[3]);

        // --- section 3 (kb1, nb1) ---
        MMA_F16(acc1[0][2], aNxt[0], b1B[0], b1B[1]);
        MMA_F16(acc1[0][3], aNxt[0], b1B[2], b1B[3]);
        MMA_F16(acc1[1][2], aNxt[1], b1B[0], b1B[1]);
        MMA_F16(acc1[1][3], aNxt[1], b1B[2], b1B[3]);
        MMA_F16(acc3[0][2], aNxt[0], b3B[0], b3B[1]);
        MMA_F16(acc3[0][3], aNxt[0], b3B[2], b3B[3]);
        MMA_F16(acc3[1][2], aNxt[1], b3B[0], b3B[1]);
        MMA_F16(acc3[1][3], aNxt[1], b3B[2], b3B[3]);

        // W half1 STS
        if (haveW) {
            *reinterpret_cast<uint4*>(smem + 1024u + stgW + wtoff + wdoff + 16) = pack8h(s0, s1);
        }
        const uint32_t t = stgRd;
        stgRd = stgW; stgW = stgCp; stgCp = t;
    }

    // --- epilogue: SwiGLU, store h as fp16 ---
    const int g = lane >> 2;
    const int tg = lane & 3;
    #pragma unroll
    for (int mb = 0; mb < 2; mb++) {
        #pragma unroll
        for (int half = 0; half < 2; half++) {
            const int r = warpM * 32 + mb * 16 + g + half * 8;
            const int s = sSlot[r];
            if (s < 0) continue;
            #pragma unroll
            for (int nb = 0; nb < 4; nb++) {
                const float v1a = acc1[mb][nb][half * 2];
                const float v1b = acc1[mb][nb][half * 2 + 1];
                const float v3a = acc3[mb][nb][half * 2];
                const float v3b = acc3[mb][nb][half * 2 + 1];
                const float ha = v1a / (1.0f + __expf(-v1a)) * v3a;
                const float hb = v1b / (1.0f + __expf(-v1b)) * v3b;
                const size_t o = (size_t)s * NI + (nBase + warpN * 32 + nb * 8 + tg * 2);
                *reinterpret_cast<uint32_t*>(g_h16 + o) = pack2h(ha, hb);
            }
        }
    }
}

// ---------------------------------------------------------------------------
// GEMM2: out[slot,:] = h[slot,:] @ w2[e]^T. Pure fp16.
// Same 3-stage / 1-barrier scheme; chunk pipelined over 2 kb sections.
// Stage tiles: A, B.
// ---------------------------------------------------------------------------
#define STAGE2B (2 * TB)                    // 20480
#define SMEM2_BYTES (1024 + 3 * STAGE2B)    // 62464

__global__ __launch_bounds__(512, 1) void gemm2_tc(
    const float* __restrict__ w2, float* __restrict__ out)
{
    const int e = blockIdx.z;
    const int ne = g_count[e];
    const int mBase = blockIdx.y * BM;
    if (mBase >= ne) return;
    const int nBase = blockIdx.x * BN;

    extern __shared__ char smem[];
    const uint32_t sb = smem_u32(smem);
    const int tid = threadIdx.x;
    const int wid = tid >> 5;
    const int lane = tid & 31;

    int* sSlot = reinterpret_cast<int*>(smem);
    if (tid < BM) {
        int m = mBase + tid;
        sSlot[tid] = (m < ne) ? g_slots[e][m] : -1;
    }
    __syncthreads();

    const int prow = tid >> 2;
    const int pcolg = tid & 3;
    const uint32_t adoff = 1024u + (uint32_t)prow * LDS_STRIDE + pcolg * 16;
    const __half* asrcp;
    {
        int s = sSlot[prow];
        int sl = (s >= 0 ? s : 0);
        asrcp = g_h16 + (size_t)sl * NI + pcolg * 8;
    }

    // W producer: 8 fp32 -> 8 fp16 per thread per chunk
    const int wrow = tid >> 2;
    const int wq   = tid & 3;
    const float* wsrc = w2 + (size_t)e * ND * NI + (size_t)(nBase + wrow) * NI + wq * 8;
    const uint32_t wdoff = (uint32_t)wrow * LDS_STRIDE + wq * 16;
    const uint32_t wtoff = TB;

    const int warpM = wid & 3;
    const int warpN = wid >> 2;
    const uint32_t aoff = (uint32_t)(warpM * 32 + (lane & 15)) * LDS_STRIDE
                        + (uint32_t)(lane >> 4) * 16;
    const uint32_t boff = (uint32_t)(warpN * 32 + (lane & 7) + ((lane >> 3) & 2) * 4) * LDS_STRIDE
                        + (uint32_t)((lane >> 3) & 1) * 16;

    float acc[2][4][4] = {};

    const int NCH = NI / BK;   // 88

    // --- prologue ---
    CP_ASYNC16(adoff + sb, asrcp);
    CP_COMMIT();
    CP_ASYNC16(adoff + sb + STAGE2B, asrcp + BK);
    CP_COMMIT();
    {
        float4 s0 = *reinterpret_cast<const float4*>(wsrc + 0);
        float4 s1 = *reinterpret_cast<const float4*>(wsrc + 4);
        *reinterpret_cast<uint4*>(smem + 1024u + wtoff + wdoff) = pack8h(s0, s1);
    }

    uint32_t stgRd = 0, stgW = STAGE2B, stgCp = 2 * STAGE2B;

    for (int c = 0; c < NCH; c++) {
        const bool haveCp = (c + 2 < NCH);
        const bool haveW  = (c + 1 < NCH);
        const int kt = (c + 1) * BK;

        if (c + 1 < NCH) { CP_WAIT(1); } else { CP_WAIT(0); }
        __syncthreads();
        if (haveCp) {
            const int kt2 = (c + 2) * BK;
            CP_ASYNC16(adoff + sb + stgCp, asrcp + kt2);
            CP_COMMIT();
        }

        const uint32_t bb = sb + 1024u + stgRd;
        const uint32_t tA = bb;
        const uint32_t tBh = bb + TB;
        const uint32_t NO = 16 * LDS_STRIDE;

        float4 s0, s1;
        if (haveW) {
            s0 = *reinterpret_cast<const float4*>(wsrc + kt + 0);
            s1 = *reinterpret_cast<const float4*>(wsrc + kt + 4);
        }

        // preload kb0
        uint32_t aCur[2][4], aNxt[2][4], bA[2][4], bB[2][4];
        LDSM4(aCur[0], tA + aoff);
        LDSM4(aCur[1], tA + aoff + NO);
        LDSM4(bA[0], tBh + boff);
        LDSM4(bA[1], tBh + boff + NO);

        // --- section kb0: prefetch kb1 ---
        LDSM4(aNxt[0], tA + aoff + 32);
        LDSM4(aNxt[1], tA + aoff + NO + 32);
        LDSM4(bB[0], tBh + boff + 32);
        LDSM4(bB[1], tBh + boff + NO + 32);
        MMA_F16(acc[0][0], aCur[0], bA[0][0], bA[0][1]);
        MMA_F16(acc[0][1], aCur[0], bA[0][2], bA[0][3]);
        MMA_F16(acc[1][0], aCur[1], bA[0][0], bA[0][1]);
        MMA_F16(acc[1][1], aCur[1], bA[0][2], bA[0][3]);
        MMA_F16(acc[0][2], aCur[0], bA[1][0], bA[1][1]);
        MMA_F16(acc[0][3], aCur[0], bA[1][2], bA[1][3]);
        MMA_F16(acc[1][2], aCur[1], bA[1][0], bA[1][1]);
        MMA_F16(acc[1][3], aCur[1], bA[1][2], bA[1][3]);

        // W STS between sections
        if (haveW) {
            *reinterpret_cast<uint4*>(smem + 1024u + stgW + wtoff + wdoff) = pack8h(s0, s1);
        }

        // --- section kb1 ---
        MMA_F16(acc[0][0], aNxt[0], bB[0][0], bB[0][1]);
        MMA_F16(acc[0][1], aNxt[0], bB[0][2], bB[0][3]);
        MMA_F16(acc[1][0], aNxt[1], bB[0][0], bB[0][1]);
        MMA_F16(acc[1][1], aNxt[1], bB[0][2], bB[0][3]);
        MMA_F16(acc[0][2], aNxt[0], bB[1][0], bB[1][1]);
        MMA_F16(acc[0][3], aNxt[0], bB[1][2], bB[1][3]);
        MMA_F16(acc[1][2], aNxt[1], bB[1][0], bB[1][1]);
        MMA_F16(acc[1][3], aNxt[1], bB[1][2], bB[1][3]);

        const uint32_t t = stgRd;
        stgRd = stgW; stgW = stgCp; stgCp = t;
    }

    // --- epilogue: fp32 direct stores ---
    const int g = lane >> 2;
    const int tg = lane & 3;
    #pragma unroll
    for (int mb = 0; mb < 2; mb++) {
        #pragma unroll
        for (int half = 0; half < 2; half++) {
            const int r = warpM * 32 + mb * 16 + g + half * 8;
            const int s = sSlot[r];
            if (s < 0) continue;
            #pragma unroll
            for (int nb = 0; nb < 4; nb++) {
                float2 v;
                v.x = acc[mb][nb][half * 2];
                v.y = acc[mb][nb][half * 2 + 1];
                const size_t o = (size_t)s * ND + (nBase + warpN * 32 + nb * 8 + tg * 2);
                *reinterpret_cast<float2*>(out + o) = v;
            }
        }
    }
}

// ---------------------------------------------------------------------------
// Launch. Inputs (metadata order): x, w1, w2, w3, expert_indices.
// ---------------------------------------------------------------------------
extern "C" void kernel_launch(void* const* d_in, const int* in_sizes, int n_in,
                              void* d_out, int out_size) {
    const float* x  = (const float*)d_in[0];
    const float* w1 = (const float*)d_in[1];
    const float* w2 = (const float*)d_in[2];
    const float* w3 = (const float*)d_in[3];
    const int*   idx = (const int*)d_in[4];
    float* out = (float*)d_out;

    cudaFuncSetAttribute(gemm1_tc, cudaFuncAttributeMaxDynamicSharedMemorySize, SMEM1_BYTES);
    cudaFuncSetAttribute(gemm2_tc, cudaFuncAttributeMaxDynamicSharedMemorySize, SMEM2_BYTES);

    __half* x16;
    cudaGetSymbolAddress((void**)&x16, g_x16);

    detect_and_zero_kernel<<<1, 256>>>(idx);
    route_kernel<<<NSLOT / 256, 256>>>(idx);

    const int nX8 = NT * ND / 8;
    conv_f16_kernel<<<nX8 / 256, 256>>>(x, x16, nX8);

    gemm1_tc<<<dim3(NI / BN, NSLOT / BM, NE), 512, SMEM1_BYTES>>>(w1, w3);
    gemm2_tc<<<dim3(ND / BN, NSLOT / BM, NE), 512, SMEM2_BYTES>>>(w2, out);
}

// round 13
// speedup vs baseline: 1.0497x; 1.0497x over previous
#include <cuda_runtime.h>
#include <cuda_fp16.h>
#include <cstdint>
#include <math.h>

// Problem constants
#define NT 1024
#define NA 2
#define NE 8
#define NI 2816
#define ND 1024
#define NSLOT (NT * NA)

// GEMM tiling: block 128x128x32, 512 threads (16 warps: 4M x 4N), 3-stage pipe
#define BM 128
#define BN 128
#define BK 32
#define LDS_STRIDE 80              // bytes per smem tile row (32*2 padded to 80)
#define TB (128 * LDS_STRIDE)      // one tile: 128 rows x 80B = 10240 B

// ---------------------------------------------------------------------------
// Device global scratch
// ---------------------------------------------------------------------------
__device__ int g_count[NE];
__device__ int g_slots[NE][NSLOT];
__device__ int g_is64;

__device__ __align__(16) __half g_x16[NT * ND];
__device__ __align__(16) __half g_h16[(size_t)NSLOT * NI];

// ---------------------------------------------------------------------------
// PTX helpers (base-target sm_103 features only)
// ---------------------------------------------------------------------------
__device__ __forceinline__ uint32_t smem_u32(const void* p) {
    uint32_t a;
    asm("{ .reg .u64 t; cvta.to.shared.u64 t, %1; cvt.u32.u64 %0, t; }"
        : "=r"(a) : "l"(p));
    return a;
}

#define LDSM4(R, addr) \
    asm volatile("ldmatrix.sync.aligned.m8n8.x4.shared.b16 {%0,%1,%2,%3}, [%4];" \
        : "=r"((R)[0]), "=r"((R)[1]), "=r"((R)[2]), "=r"((R)[3]) : "r"(addr))

#define MMA_F16(C, A, B0, B1) \
    asm volatile("mma.sync.aligned.m16n8k16.row.col.f32.f16.f16.f32 " \
        "{%0,%1,%2,%3}, {%4,%5,%6,%7}, {%8,%9}, {%0,%1,%2,%3};" \
        : "+f"((C)[0]), "+f"((C)[1]), "+f"((C)[2]), "+f"((C)[3]) \
        : "r"((A)[0]), "r"((A)[1]), "r"((A)[2]), "r"((A)[3]), "r"(B0), "r"(B1))

#define CP_ASYNC16(dst, src) \
    asm volatile("cp.async.cg.shared.global [%0], [%1], 16;" :: "r"(dst), "l"(src))
#define CP_COMMIT() asm volatile("cp.async.commit_group;" ::: "memory")
#define CP_WAIT(N) asm volatile("cp.async.wait_group %0;" :: "n"(N) : "memory")
#define PREFETCH_L2(p) asm volatile("prefetch.global.L2 [%0];" :: "l"(p))

__device__ __forceinline__ uint32_t pack2h(float a, float b) {
    __half2 h = __floats2half2_rn(a, b);
    return *reinterpret_cast<uint32_t*>(&h);
}
// 8 fp32 -> 8 packed fp16 (uint4)
__device__ __forceinline__ uint4 pack8h(const float4& a, const float4& b) {
    uint4 r;
    r.x = pack2h(a.x, a.y);
    r.y = pack2h(a.z, a.w);
    r.z = pack2h(b.x, b.y);
    r.w = pack2h(b.z, b.w);
    return r;
}

// ---------------------------------------------------------------------------
// Routing
// ---------------------------------------------------------------------------
__global__ void detect_and_zero_kernel(const int* __restrict__ idx32) {
    __shared__ int any;
    if (threadIdx.x == 0) any = 0;
    if (threadIdx.x < NE) g_count[threadIdx.x] = 0;
    __syncthreads();
    int local = 0;
    for (int i = threadIdx.x; i < NSLOT / 2; i += blockDim.x)
        local |= idx32[2 * i + 1];
    if (local) atomicOr(&any, 1);
    __syncthreads();
    if (threadIdx.x == 0) g_is64 = (any == 0) ? 1 : 0;
}

__global__ void route_kernel(const int* __restrict__ idx32) {
    int s = blockIdx.x * blockDim.x + threadIdx.x;
    if (s < NSLOT) {
        int e = g_is64 ? idx32[2 * s] : idx32[s];
        e &= (NE - 1);
        int p = atomicAdd(&g_count[e], 1);
        g_slots[e][p] = s;
    }
}

// ---------------------------------------------------------------------------
// x: fp32 -> fp16 (tiny)
// ---------------------------------------------------------------------------
__global__ __launch_bounds__(256) void conv_f16_kernel(
    const float* __restrict__ src, __half* __restrict__ dst, int n8)
{
    int i = blockIdx.x * blockDim.x + threadIdx.x;
    if (i >= n8) return;
    float4 a = reinterpret_cast<const float4*>(src)[2 * i];
    float4 b = reinterpret_cast<const float4*>(src)[2 * i + 1];
    reinterpret_cast<uint4*>(dst)[i] = pack8h(a, b);
}

// ---------------------------------------------------------------------------
// GEMM1: h = silu(X @ w1[e]^T) * (X @ w3[e]^T). Pure fp16, fp32 acc.
// 3-stage pipeline, ONE barrier per chunk (R7/R11 skeleton); W LDG hoisted
// above the barrier + L2 prefetch for chunk c+2.
// Stage tiles: A, B1, B3 (each 128 x 32 fp16, 80B stride)
// ---------------------------------------------------------------------------
#define STAGE1B (3 * TB)                    // 30720
#define SMEM1_BYTES (1024 + 3 * STAGE1B)    // 93184

__global__ __launch_bounds__(512, 1) void gemm1_tc(
    const float* __restrict__ w1, const float* __restrict__ w3)
{
    const int e = blockIdx.z;
    const int ne = g_count[e];
    const int mBase = blockIdx.y * BM;
    if (mBase >= ne) return;
    const int nBase = blockIdx.x * BN;

    extern __shared__ char smem[];
    const uint32_t sb = smem_u32(smem);
    const int tid = threadIdx.x;
    const int wid = tid >> 5;
    const int lane = tid & 31;

    int* sSlot = reinterpret_cast<int*>(smem);
    if (tid < BM) {
        int m = mBase + tid;
        sSlot[tid] = (m < ne) ? g_slots[e][m] : -1;
    }
    __syncthreads();

    // --- A producer: one 16B granule per thread ---
    const int prow = tid >> 2;
    const int pcolg = tid & 3;
    const uint32_t adoff = 1024u + (uint32_t)prow * LDS_STRIDE + pcolg * 16;
    const __half* asrcp;
    {
        int s = sSlot[prow];
        int tok = (s >= 0 ? s : 0) >> 1;
        asrcp = g_x16 + (size_t)tok * ND + pcolg * 8;
    }

    // --- W producer: 16 fp32 -> 16 fp16 per thread per chunk (w1 or w3) ---
    const int wt    = tid >> 8;            // 0: w1, 1: w3
    const int wrow  = (tid & 255) >> 1;    // 0..127
    const int whalf = tid & 1;             // 16 floats each
    const float* wsrc = (wt == 0 ? w1 : w3)
        + (size_t)e * NI * ND + (size_t)(nBase + wrow) * ND + whalf * 16;
    const uint32_t wdoff = (uint32_t)wrow * LDS_STRIDE + whalf * 32;
    const uint32_t wtoff = (uint32_t)(1 + wt) * TB;   // B1 or B3 within stage

    // --- consumer: 16 warps = 4M x 4N, warp tile 32x32 ---
    const int warpM = wid & 3;
    const int warpN = wid >> 2;
    const uint32_t aoff = (uint32_t)(warpM * 32 + (lane & 15)) * LDS_STRIDE
                        + (uint32_t)(lane >> 4) * 16;
    const uint32_t boff = (uint32_t)(warpN * 32 + (lane & 7) + ((lane >> 3) & 2) * 4) * LDS_STRIDE
                        + (uint32_t)((lane >> 3) & 1) * 16;

    float acc1[2][4][4] = {};
    float acc3[2][4][4] = {};

    const int NCH = ND / BK;   // 32

    // --- prologue: cp A for chunks 0,1 (stages 0,1); convert+store W chunk 0 ---
    CP_ASYNC16(adoff + sb, asrcp);
    CP_COMMIT();
    CP_ASYNC16(adoff + sb + STAGE1B, asrcp + BK);
    CP_COMMIT();
    {
        float4 s0 = *reinterpret_cast<const float4*>(wsrc + 0);
        float4 s1 = *reinterpret_cast<const float4*>(wsrc + 4);
        float4 s2 = *reinterpret_cast<const float4*>(wsrc + 8);
        float4 s3 = *reinterpret_cast<const float4*>(wsrc + 12);
        *reinterpret_cast<uint4*>(smem + 1024u + wtoff + wdoff)      = pack8h(s0, s1);
        *reinterpret_cast<uint4*>(smem + 1024u + wtoff + wdoff + 16) = pack8h(s2, s3);
    }
    PREFETCH_L2(wsrc + BK);
    PREFETCH_L2(wsrc + BK + 8);

    uint32_t stgRd = 0, stgW = STAGE1B, stgCp = 2 * STAGE1B;

    for (int c = 0; c < NCH; c++) {
        const bool haveCp = (c + 2 < NCH);
        const bool haveW  = (c + 1 < NCH);

        // W LDG for chunk c+1 issued BEFORE the wait/barrier: no smem hazard,
        // latency overlaps barrier + MMA section instead of just the tail.
        float4 s0, s1, s2, s3;
        if (haveW) {
            const int kt = (c + 1) * BK;
            s0 = *reinterpret_cast<const float4*>(wsrc + kt + 0);
            s1 = *reinterpret_cast<const float4*>(wsrc + kt + 4);
            s2 = *reinterpret_cast<const float4*>(wsrc + kt + 8);
            s3 = *reinterpret_cast<const float4*>(wsrc + kt + 12);
        }
        if (haveCp) {
            // L2 prefetch for chunk c+2's W lines (zero register cost)
            const int kt2 = (c + 2) * BK;
            PREFETCH_L2(wsrc + kt2);
            PREFETCH_L2(wsrc + kt2 + 8);
        }

        if (c + 1 < NCH) { CP_WAIT(1); } else { CP_WAIT(0); }
        __syncthreads();
        if (haveCp) {
            const int kt2 = (c + 2) * BK;
            CP_ASYNC16(adoff + sb + stgCp, asrcp + kt2);
            CP_COMMIT();
        }

        const uint32_t bb = sb + 1024u + stgRd;
        const uint32_t tA = bb;
        const uint32_t tB1 = bb + TB, tB3 = bb + 2 * TB;

        #pragma unroll
        for (int kb = 0; kb < 2; kb++) {
            const uint32_t ko = kb * 32;
            uint32_t a[2][4];
            #pragma unroll
            for (int mb = 0; mb < 2; mb++)
                LDSM4(a[mb], tA + aoff + mb * (16 * LDS_STRIDE) + ko);
            #pragma unroll
            for (int nb2 = 0; nb2 < 2; nb2++) {
                const uint32_t no = nb2 * (16 * LDS_STRIDE);
                const int j0 = 2 * nb2, j1 = 2 * nb2 + 1;
                uint32_t b1[4], b3[4];
                LDSM4(b1, tB1 + boff + no + ko);
                LDSM4(b3, tB3 + boff + no + ko);
                // 8 distinct C targets
                MMA_F16(acc1[0][j0], a[0], b1[0], b1[1]);
                MMA_F16(acc1[0][j1], a[0], b1[2], b1[3]);
                MMA_F16(acc1[1][j0], a[1], b1[0], b1[1]);
                MMA_F16(acc1[1][j1], a[1], b1[2], b1[3]);
                MMA_F16(acc3[0][j0], a[0], b3[0], b3[1]);
                MMA_F16(acc3[0][j1], a[0], b3[2], b3[3]);
                MMA_F16(acc3[1][j0], a[1], b3[0], b3[1]);
                MMA_F16(acc3[1][j1], a[1], b3[2], b3[3]);
            }
        }

        if (haveW) {
            *reinterpret_cast<uint4*>(smem + 1024u + stgW + wtoff + wdoff)      = pack8h(s0, s1);
            *reinterpret_cast<uint4*>(smem + 1024u + stgW + wtoff + wdoff + 16) = pack8h(s2, s3);
        }
        const uint32_t t = stgRd;
        stgRd = stgW; stgW = stgCp; stgCp = t;
    }

    // --- epilogue: SwiGLU, store h as fp16 ---
    const int g = lane >> 2;
    const int tg = lane & 3;
    #pragma unroll
    for (int mb = 0; mb < 2; mb++) {
        #pragma unroll
        for (int half = 0; half < 2; half++) {
            const int r = warpM * 32 + mb * 16 + g + half * 8;
            const int s = sSlot[r];
            if (s < 0) continue;
            #pragma unroll
            for (int nb = 0; nb < 4; nb++) {
                const float v1a = acc1[mb][nb][half * 2];
                const float v1b = acc1[mb][nb][half * 2 + 1];
                const float v3a = acc3[mb][nb][half * 2];
                const float v3b = acc3[mb][nb][half * 2 + 1];
                const float ha = v1a / (1.0f + __expf(-v1a)) * v3a;
                const float hb = v1b / (1.0f + __expf(-v1b)) * v3b;
                const size_t o = (size_t)s * NI + (nBase + warpN * 32 + nb * 8 + tg * 2);
                *reinterpret_cast<uint32_t*>(g_h16 + o) = pack2h(ha, hb);
            }
        }
    }
}

// ---------------------------------------------------------------------------
// GEMM2: out[slot,:] = h[slot,:] @ w2[e]^T. Pure fp16.
// Same 3-stage / 1-barrier scheme; W LDG hoisted + L2 prefetch.
// Stage tiles: A, B.
// ---------------------------------------------------------------------------
#define STAGE2B (2 * TB)                    // 20480
#define SMEM2_BYTES (1024 + 3 * STAGE2B)    // 62464

__global__ __launch_bounds__(512, 1) void gemm2_tc(
    const float* __restrict__ w2, float* __restrict__ out)
{
    const int e = blockIdx.z;
    const int ne = g_count[e];
    const int mBase = blockIdx.y * BM;
    if (mBase >= ne) return;
    const int nBase = blockIdx.x * BN;

    extern __shared__ char smem[];
    const uint32_t sb = smem_u32(smem);
    const int tid = threadIdx.x;
    const int wid = tid >> 5;
    const int lane = tid & 31;

    int* sSlot = reinterpret_cast<int*>(smem);
    if (tid < BM) {
        int m = mBase + tid;
        sSlot[tid] = (m < ne) ? g_slots[e][m] : -1;
    }
    __syncthreads();

    const int prow = tid >> 2;
    const int pcolg = tid & 3;
    const uint32_t adoff = 1024u + (uint32_t)prow * LDS_STRIDE + pcolg * 16;
    const __half* asrcp;
    {
        int s = sSlot[prow];
        int sl = (s >= 0 ? s : 0);
        asrcp = g_h16 + (size_t)sl * NI + pcolg * 8;
    }

    // W producer: 8 fp32 -> 8 fp16 per thread per chunk
    const int wrow = tid >> 2;
    const int wq   = tid & 3;
    const float* wsrc = w2 + (size_t)e * ND * NI + (size_t)(nBase + wrow) * NI + wq * 8;
    const uint32_t wdoff = (uint32_t)wrow * LDS_STRIDE + wq * 16;
    const uint32_t wtoff = TB;

    const int warpM = wid & 3;
    const int warpN = wid >> 2;
    const uint32_t aoff = (uint32_t)(warpM * 32 + (lane & 15)) * LDS_STRIDE
                        + (uint32_t)(lane >> 4) * 16;
    const uint32_t boff = (uint32_t)(warpN * 32 + (lane & 7) + ((lane >> 3) & 2) * 4) * LDS_STRIDE
                        + (uint32_t)((lane >> 3) & 1) * 16;

    float acc[2][4][4] = {};

    const int NCH = NI / BK;   // 88

    // --- prologue ---
    CP_ASYNC16(adoff + sb, asrcp);
    CP_COMMIT();
    CP_ASYNC16(adoff + sb + STAGE2B, asrcp + BK);
    CP_COMMIT();
    {
        float4 s0 = *reinterpret_cast<const float4*>(wsrc + 0);
        float4 s1 = *reinterpret_cast<const float4*>(wsrc + 4);
        *reinterpret_cast<uint4*>(smem + 1024u + wtoff + wdoff) = pack8h(s0, s1);
    }
    PREFETCH_L2(wsrc + BK);

    uint32_t stgRd = 0, stgW = STAGE2B, stgCp = 2 * STAGE2B;

    for (int c = 0; c < NCH; c++) {
        const bool haveCp = (c + 2 < NCH);
        const bool haveW  = (c + 1 < NCH);

        // Hoisted W LDG (chunk c+1) + L2 prefetch (chunk c+2)
        float4 s0, s1;
        if (haveW) {
            const int kt = (c + 1) * BK;
            s0 = *reinterpret_cast<const float4*>(wsrc + kt + 0);
            s1 = *reinterpret_cast<const float4*>(wsrc + kt + 4);
        }
        if (haveCp) {
            PREFETCH_L2(wsrc + (c + 2) * BK);
        }

        if (c + 1 < NCH) { CP_WAIT(1); } else { CP_WAIT(0); }
        __syncthreads();
        if (haveCp) {
            const int kt2 = (c + 2) * BK;
            CP_ASYNC16(adoff + sb + stgCp, asrcp + kt2);
            CP_COMMIT();
        }

        const uint32_t bb = sb + 1024u + stgRd;
        const uint32_t tA = bb;
        const uint32_t tBh = bb + TB;

        #pragma unroll
        for (int kb = 0; kb < 2; kb++) {
            const uint32_t ko = kb * 32;
            uint32_t a[2][4];
            #pragma unroll
            for (int mb = 0; mb < 2; mb++)
                LDSM4(a[mb], tA + aoff + mb * (16 * LDS_STRIDE) + ko);
            uint32_t bh0[4], bh1[4];
            LDSM4(bh0, tBh + boff + ko);
            LDSM4(bh1, tBh + boff + 16 * LDS_STRIDE + ko);
            MMA_F16(acc[0][0], a[0], bh0[0], bh0[1]);
            MMA_F16(acc[0][1], a[0], bh0[2], bh0[3]);
            MMA_F16(acc[1][0], a[1], bh0[0], bh0[1]);
            MMA_F16(acc[1][1], a[1], bh0[2], bh0[3]);
            MMA_F16(acc[0][2], a[0], bh1[0], bh1[1]);
            MMA_F16(acc[0][3], a[0], bh1[2], bh1[3]);
            MMA_F16(acc[1][2], a[1], bh1[0], bh1[1]);
            MMA_F16(acc[1][3], a[1], bh1[2], bh1[3]);
        }

        if (haveW) {
            *reinterpret_cast<uint4*>(smem + 1024u + stgW + wtoff + wdoff) = pack8h(s0, s1);
        }
        const uint32_t t = stgRd;
        stgRd = stgW; stgW = stgCp; stgCp = t;
    }

    // --- epilogue: fp32 direct stores ---
    const int g = lane >> 2;
    const int tg = lane & 3;
    #pragma unroll
    for (int mb = 0; mb < 2; mb++) {
        #pragma unroll
        for (int half = 0; half < 2; half++) {
            const int r = warpM * 32 + mb * 16 + g + half * 8;
            const int s = sSlot[r];
            if (s < 0) continue;
            #pragma unroll
            for (int nb = 0; nb < 4; nb++) {
                float2 v;
                v.x = acc[mb][nb][half * 2];
                v.y = acc[mb][nb][half * 2 + 1];
                const size_t o = (size_t)s * ND + (nBase + warpN * 32 + nb * 8 + tg * 2);
                *reinterpret_cast<float2*>(out + o) = v;
            }
        }
    }
}

// ---------------------------------------------------------------------------
// Launch. Inputs (metadata order): x, w1, w2, w3, expert_indices.
// ---------------------------------------------------------------------------
extern "C" void kernel_launch(void* const* d_in, const int* in_sizes, int n_in,
                              void* d_out, int out_size) {
    const float* x  = (const float*)d_in[0];
    const float* w1 = (const float*)d_in[1];
    const float* w2 = (const float*)d_in[2];
    const float* w3 = (const float*)d_in[3];
    const int*   idx = (const int*)d_in[4];
    float* out = (float*)d_out;

    cudaFuncSetAttribute(gemm1_tc, cudaFuncAttributeMaxDynamicSharedMemorySize, SMEM1_BYTES);
    cudaFuncSetAttribute(gemm2_tc, cudaFuncAttributeMaxDynamicSharedMemorySize, SMEM2_BYTES);

    __half* x16;
    cudaGetSymbolAddress((void**)&x16, g_x16);

    detect_and_zero_kernel<<<1, 256>>>(idx);
    route_kernel<<<NSLOT / 256, 256>>>(idx);

    const int nX8 = NT * ND / 8;
    conv_f16_kernel<<<nX8 / 256, 256>>>(x, x16, nX8);

    gemm1_tc<<<dim3(NI / BN, NSLOT / BM, NE), 512, SMEM1_BYTES>>>(w1, w3);
    gemm2_tc<<<dim3(ND / BN, NSLOT / BM, NE), 512, SMEM2_BYTES>>>(w2, out);
}

// round 14
// speedup vs baseline: 1.0509x; 1.0011x over previous
#include <cuda_runtime.h>
#include <cuda_fp16.h>
#include <cstdint>
#include <math.h>

// Problem constants
#define NT 1024
#define NA 2
#define NE 8
#define NI 2816
#define ND 1024
#define NSLOT (NT * NA)

// GEMM tiling: gemm1 block 128x128x32 (512 thr); gemm2 block 64x128x32 (256 thr)
#define BM 128
#define BM2 64
#define BN 128
#define BK 32
#define LDS_STRIDE 80              // bytes per smem tile row (32*2 padded to 80)
#define TB (128 * LDS_STRIDE)      // 128-row tile: 10240 B
#define TBA2 (64 * LDS_STRIDE)     // 64-row tile: 5120 B

// ---------------------------------------------------------------------------
// Device global scratch
// ---------------------------------------------------------------------------
__device__ int g_count[NE];
__device__ int g_slots[NE][NSLOT];
__device__ int g_is64;

__device__ __align__(16) __half g_x16[NT * ND];
__device__ __align__(16) __half g_h16[(size_t)NSLOT * NI];

// ---------------------------------------------------------------------------
// PTX helpers (base-target sm_103 features only)
// ---------------------------------------------------------------------------
__device__ __forceinline__ uint32_t smem_u32(const void* p) {
    uint32_t a;
    asm("{ .reg .u64 t; cvta.to.shared.u64 t, %1; cvt.u32.u64 %0, t; }"
        : "=r"(a) : "l"(p));
    return a;
}

#define LDSM4(R, addr) \
    asm volatile("ldmatrix.sync.aligned.m8n8.x4.shared.b16 {%0,%1,%2,%3}, [%4];" \
        : "=r"((R)[0]), "=r"((R)[1]), "=r"((R)[2]), "=r"((R)[3]) : "r"(addr))

#define MMA_F16(C, A, B0, B1) \
    asm volatile("mma.sync.aligned.m16n8k16.row.col.f32.f16.f16.f32 " \
        "{%0,%1,%2,%3}, {%4,%5,%6,%7}, {%8,%9}, {%0,%1,%2,%3};" \
        : "+f"((C)[0]), "+f"((C)[1]), "+f"((C)[2]), "+f"((C)[3]) \
        : "r"((A)[0]), "r"((A)[1]), "r"((A)[2]), "r"((A)[3]), "r"(B0), "r"(B1))

#define CP_ASYNC16(dst, src) \
    asm volatile("cp.async.cg.shared.global [%0], [%1], 16;" :: "r"(dst), "l"(src))
#define CP_COMMIT() asm volatile("cp.async.commit_group;" ::: "memory")
#define CP_WAIT(N) asm volatile("cp.async.wait_group %0;" :: "n"(N) : "memory")

__device__ __forceinline__ uint32_t pack2h(float a, float b) {
    __half2 h = __floats2half2_rn(a, b);
    return *reinterpret_cast<uint32_t*>(&h);
}
// 8 fp32 -> 8 packed fp16 (uint4)
__device__ __forceinline__ uint4 pack8h(const float4& a, const float4& b) {
    uint4 r;
    r.x = pack2h(a.x, a.y);
    r.y = pack2h(a.z, a.w);
    r.z = pack2h(b.x, b.y);
    r.w = pack2h(b.z, b.w);
    return r;
}

// ---------------------------------------------------------------------------
// Routing
// ---------------------------------------------------------------------------
__global__ void detect_and_zero_kernel(const int* __restrict__ idx32) {
    __shared__ int any;
    if (threadIdx.x == 0) any = 0;
    if (threadIdx.x < NE) g_count[threadIdx.x] = 0;
    __syncthreads();
    int local = 0;
    for (int i = threadIdx.x; i < NSLOT / 2; i += blockDim.x)
        local |= idx32[2 * i + 1];
    if (local) atomicOr(&any, 1);
    __syncthreads();
    if (threadIdx.x == 0) g_is64 = (any == 0) ? 1 : 0;
}

__global__ void route_kernel(const int* __restrict__ idx32) {
    int s = blockIdx.x * blockDim.x + threadIdx.x;
    if (s < NSLOT) {
        int e = g_is64 ? idx32[2 * s] : idx32[s];
        e &= (NE - 1);
        int p = atomicAdd(&g_count[e], 1);
        g_slots[e][p] = s;
    }
}

// ---------------------------------------------------------------------------
// x: fp32 -> fp16 (tiny)
// ---------------------------------------------------------------------------
__global__ __launch_bounds__(256) void conv_f16_kernel(
    const float* __restrict__ src, __half* __restrict__ dst, int n8)
{
    int i = blockIdx.x * blockDim.x + threadIdx.x;
    if (i >= n8) return;
    float4 a = reinterpret_cast<const float4*>(src)[2 * i];
    float4 b = reinterpret_cast<const float4*>(src)[2 * i + 1];
    reinterpret_cast<uint4*>(dst)[i] = pack8h(a, b);
}

// ---------------------------------------------------------------------------
// GEMM1: h = silu(X @ w1[e]^T) * (X @ w3[e]^T). Pure fp16, fp32 acc.
// 3-stage pipeline, ONE barrier per chunk (R11 exact):
//   CP_WAIT -> __syncthreads -> cp.async(c+2) -> W LDG(c+1) -> MMA(c) -> W STS(c+1)
// Stage tiles: A, B1, B3 (each 128 x 32 fp16, 80B stride)
// ---------------------------------------------------------------------------
#define STAGE1B (3 * TB)                    // 30720
#define SMEM1_BYTES (1024 + 3 * STAGE1B)    // 93184

__global__ __launch_bounds__(512, 1) void gemm1_tc(
    const float* __restrict__ w1, const float* __restrict__ w3)
{
    const int e = blockIdx.z;
    const int ne = g_count[e];
    const int mBase = blockIdx.y * BM;
    if (mBase >= ne) return;
    const int nBase = blockIdx.x * BN;

    extern __shared__ char smem[];
    const uint32_t sb = smem_u32(smem);
    const int tid = threadIdx.x;
    const int wid = tid >> 5;
    const int lane = tid & 31;

    int* sSlot = reinterpret_cast<int*>(smem);
    if (tid < BM) {
        int m = mBase + tid;
        sSlot[tid] = (m < ne) ? g_slots[e][m] : -1;
    }
    __syncthreads();

    // --- A producer: one 16B granule per thread ---
    const int prow = tid >> 2;
    const int pcolg = tid & 3;
    const uint32_t adoff = 1024u + (uint32_t)prow * LDS_STRIDE + pcolg * 16;
    const __half* asrcp;
    {
        int s = sSlot[prow];
        int tok = (s >= 0 ? s : 0) >> 1;
        asrcp = g_x16 + (size_t)tok * ND + pcolg * 8;
    }

    // --- W producer: 16 fp32 -> 16 fp16 per thread per chunk (w1 or w3) ---
    const int wt    = tid >> 8;            // 0: w1, 1: w3
    const int wrow  = (tid & 255) >> 1;    // 0..127
    const int whalf = tid & 1;             // 16 floats each
    const float* wsrc = (wt == 0 ? w1 : w3)
        + (size_t)e * NI * ND + (size_t)(nBase + wrow) * ND + whalf * 16;
    const uint32_t wdoff = (uint32_t)wrow * LDS_STRIDE + whalf * 32;
    const uint32_t wtoff = (uint32_t)(1 + wt) * TB;   // B1 or B3 within stage

    // --- consumer: 16 warps = 4M x 4N, warp tile 32x32 ---
    const int warpM = wid & 3;
    const int warpN = wid >> 2;
    const uint32_t aoff = (uint32_t)(warpM * 32 + (lane & 15)) * LDS_STRIDE
                        + (uint32_t)(lane >> 4) * 16;
    const uint32_t boff = (uint32_t)(warpN * 32 + (lane & 7) + ((lane >> 3) & 2) * 4) * LDS_STRIDE
                        + (uint32_t)((lane >> 3) & 1) * 16;

    float acc1[2][4][4] = {};
    float acc3[2][4][4] = {};

    const int NCH = ND / BK;   // 32

    // --- prologue: cp A for chunks 0,1 (stages 0,1); convert+store W chunk 0 ---
    CP_ASYNC16(adoff + sb, asrcp);
    CP_COMMIT();
    CP_ASYNC16(adoff + sb + STAGE1B, asrcp + BK);
    CP_COMMIT();
    {
        float4 s0 = *reinterpret_cast<const float4*>(wsrc + 0);
        float4 s1 = *reinterpret_cast<const float4*>(wsrc + 4);
        float4 s2 = *reinterpret_cast<const float4*>(wsrc + 8);
        float4 s3 = *reinterpret_cast<const float4*>(wsrc + 12);
        *reinterpret_cast<uint4*>(smem + 1024u + wtoff + wdoff)      = pack8h(s0, s1);
        *reinterpret_cast<uint4*>(smem + 1024u + wtoff + wdoff + 16) = pack8h(s2, s3);
    }

    uint32_t stgRd = 0, stgW = STAGE1B, stgCp = 2 * STAGE1B;

    for (int c = 0; c < NCH; c++) {
        const bool haveCp = (c + 2 < NCH);
        const bool haveW  = (c + 1 < NCH);

        if (c + 1 < NCH) { CP_WAIT(1); } else { CP_WAIT(0); }
        __syncthreads();
        if (haveCp) {
            const int kt2 = (c + 2) * BK;
            CP_ASYNC16(adoff + sb + stgCp, asrcp + kt2);
            CP_COMMIT();
        }
        float4 s0, s1, s2, s3;
        if (haveW) {
            const int kt = (c + 1) * BK;
            s0 = *reinterpret_cast<const float4*>(wsrc + kt + 0);
            s1 = *reinterpret_cast<const float4*>(wsrc + kt + 4);
            s2 = *reinterpret_cast<const float4*>(wsrc + kt + 8);
            s3 = *reinterpret_cast<const float4*>(wsrc + kt + 12);
        }

        const uint32_t bb = sb + 1024u + stgRd;
        const uint32_t tA = bb;
        const uint32_t tB1 = bb + TB, tB3 = bb + 2 * TB;

        #pragma unroll
        for (int kb = 0; kb < 2; kb++) {
            const uint32_t ko = kb * 32;
            uint32_t a[2][4];
            #pragma unroll
            for (int mb = 0; mb < 2; mb++)
                LDSM4(a[mb], tA + aoff + mb * (16 * LDS_STRIDE) + ko);
            #pragma unroll
            for (int nb2 = 0; nb2 < 2; nb2++) {
                const uint32_t no = nb2 * (16 * LDS_STRIDE);
                const int j0 = 2 * nb2, j1 = 2 * nb2 + 1;
                uint32_t b1[4], b3[4];
                LDSM4(b1, tB1 + boff + no + ko);
                LDSM4(b3, tB3 + boff + no + ko);
                // 8 distinct C targets
                MMA_F16(acc1[0][j0], a[0], b1[0], b1[1]);
                MMA_F16(acc1[0][j1], a[0], b1[2], b1[3]);
                MMA_F16(acc1[1][j0], a[1], b1[0], b1[1]);
                MMA_F16(acc1[1][j1], a[1], b1[2], b1[3]);
                MMA_F16(acc3[0][j0], a[0], b3[0], b3[1]);
                MMA_F16(acc3[0][j1], a[0], b3[2], b3[3]);
                MMA_F16(acc3[1][j0], a[1], b3[0], b3[1]);
                MMA_F16(acc3[1][j1], a[1], b3[2], b3[3]);
            }
        }

        if (haveW) {
            *reinterpret_cast<uint4*>(smem + 1024u + stgW + wtoff + wdoff)      = pack8h(s0, s1);
            *reinterpret_cast<uint4*>(smem + 1024u + stgW + wtoff + wdoff + 16) = pack8h(s2, s3);
        }
        const uint32_t t = stgRd;
        stgRd = stgW; stgW = stgCp; stgCp = t;
    }

    // --- epilogue: SwiGLU, store h as fp16 ---
    const int g = lane >> 2;
    const int tg = lane & 3;
    #pragma unroll
    for (int mb = 0; mb < 2; mb++) {
        #pragma unroll
        for (int half = 0; half < 2; half++) {
            const int r = warpM * 32 + mb * 16 + g + half * 8;
            const int s = sSlot[r];
            if (s < 0) continue;
            #pragma unroll
            for (int nb = 0; nb < 4; nb++) {
                const float v1a = acc1[mb][nb][half * 2];
                const float v1b = acc1[mb][nb][half * 2 + 1];
                const float v3a = acc3[mb][nb][half * 2];
                const float v3b = acc3[mb][nb][half * 2 + 1];
                const float ha = v1a / (1.0f + __expf(-v1a)) * v3a;
                const float hb = v1b / (1.0f + __expf(-v1b)) * v3b;
                const size_t o = (size_t)s * NI + (nBase + warpN * 32 + nb * 8 + tg * 2);
                *reinterpret_cast<uint32_t*>(g_h16 + o) = pack2h(ha, hb);
            }
        }
    }
}

// ---------------------------------------------------------------------------
// GEMM2: out[slot,:] = h[slot,:] @ w2[e]^T. Pure fp16.
// Block 64(M) x 128(N), 256 threads (8 warps = 2M x 4N, warp tile 32x32 —
// identical per-warp schedule to R11), 2 CTAs/SM. Effective grid ~264 CTAs
// -> single wave (was 160 CTAs -> 2 waves).
// Stage tiles: A (64 rows), B (128 rows). 3-stage / 1-barrier (R11 scheme).
// ---------------------------------------------------------------------------
#define STAGE2B (TBA2 + TB)                 // 15360
#define SMEM2_BYTES (1024 + 3 * STAGE2B)    // 47104

__global__ __launch_bounds__(256, 2) void gemm2_tc(
    const float* __restrict__ w2, float* __restrict__ out)
{
    const int e = blockIdx.z;
    const int ne = g_count[e];
    const int mBase = blockIdx.y * BM2;
    if (mBase >= ne) return;
    const int nBase = blockIdx.x * BN;

    extern __shared__ char smem[];
    const uint32_t sb = smem_u32(smem);
    const int tid = threadIdx.x;
    const int wid = tid >> 5;
    const int lane = tid & 31;

    int* sSlot = reinterpret_cast<int*>(smem);
    if (tid < BM2) {
        int m = mBase + tid;
        sSlot[tid] = (m < ne) ? g_slots[e][m] : -1;
    }
    __syncthreads();

    // --- A producer: one 16B granule per thread (64 rows x 4 granules = 256) ---
    const int prow = tid >> 2;
    const int pcolg = tid & 3;
    const uint32_t adoff = 1024u + (uint32_t)prow * LDS_STRIDE + pcolg * 16;
    const __half* asrcp;
    {
        int s = sSlot[prow];
        int sl = (s >= 0 ? s : 0);
        asrcp = g_h16 + (size_t)sl * NI + pcolg * 8;
    }

    // --- W producer: 16 fp32 -> 16 fp16 per thread per chunk (128 rows x 2 halves) ---
    const int wrow  = tid >> 1;            // 0..127
    const int whalf = tid & 1;             // 16 floats each
    const float* wsrc = w2 + (size_t)e * ND * NI + (size_t)(nBase + wrow) * NI + whalf * 16;
    const uint32_t wdoff = (uint32_t)wrow * LDS_STRIDE + whalf * 32;
    const uint32_t wtoff = TBA2;           // B tile after the 64-row A tile

    // --- consumer: 8 warps = 2M x 4N, warp tile 32x32 ---
    const int warpM = wid & 1;
    const int warpN = wid >> 1;
    const uint32_t aoff = (uint32_t)(warpM * 32 + (lane & 15)) * LDS_STRIDE
                        + (uint32_t)(lane >> 4) * 16;
    const uint32_t boff = (uint32_t)(warpN * 32 + (lane & 7) + ((lane >> 3) & 2) * 4) * LDS_STRIDE
                        + (uint32_t)((lane >> 3) & 1) * 16;

    float acc[2][4][4] = {};

    const int NCH = NI / BK;   // 88

    // --- prologue ---
    CP_ASYNC16(adoff + sb, asrcp);
    CP_COMMIT();
    CP_ASYNC16(adoff + sb + STAGE2B, asrcp + BK);
    CP_COMMIT();
    {
        float4 s0 = *reinterpret_cast<const float4*>(wsrc + 0);
        float4 s1 = *reinterpret_cast<const float4*>(wsrc + 4);
        float4 s2 = *reinterpret_cast<const float4*>(wsrc + 8);
        float4 s3 = *reinterpret_cast<const float4*>(wsrc + 12);
        *reinterpret_cast<uint4*>(smem + 1024u + wtoff + wdoff)      = pack8h(s0, s1);
        *reinterpret_cast<uint4*>(smem + 1024u + wtoff + wdoff + 16) = pack8h(s2, s3);
    }

    uint32_t stgRd = 0, stgW = STAGE2B, stgCp = 2 * STAGE2B;

    for (int c = 0; c < NCH; c++) {
        const bool haveCp = (c + 2 < NCH);
        const bool haveW  = (c + 1 < NCH);

        if (c + 1 < NCH) { CP_WAIT(1); } else { CP_WAIT(0); }
        __syncthreads();
        if (haveCp) {
            const int kt2 = (c + 2) * BK;
            CP_ASYNC16(adoff + sb + stgCp, asrcp + kt2);
            CP_COMMIT();
        }
        float4 s0, s1, s2, s3;
        if (haveW) {
            const int kt = (c + 1) * BK;
            s0 = *reinterpret_cast<const float4*>(wsrc + kt + 0);
            s1 = *reinterpret_cast<const float4*>(wsrc + kt + 4);
            s2 = *reinterpret_cast<const float4*>(wsrc + kt + 8);
            s3 = *reinterpret_cast<const float4*>(wsrc + kt + 12);
        }

        const uint32_t bb = sb + 1024u + stgRd;
        const uint32_t tA = bb;
        const uint32_t tBh = bb + TBA2;

        #pragma unroll
        for (int kb = 0; kb < 2; kb++) {
            const uint32_t ko = kb * 32;
            uint32_t a[2][4];
            #pragma unroll
            for (int mb = 0; mb < 2; mb++)
                LDSM4(a[mb], tA + aoff + mb * (16 * LDS_STRIDE) + ko);
            uint32_t bh0[4], bh1[4];
            LDSM4(bh0, tBh + boff + ko);
            LDSM4(bh1, tBh + boff + 16 * LDS_STRIDE + ko);
            MMA_F16(acc[0][0], a[0], bh0[0], bh0[1]);
            MMA_F16(acc[0][1], a[0], bh0[2], bh0[3]);
            MMA_F16(acc[1][0], a[1], bh0[0], bh0[1]);
            MMA_F16(acc[1][1], a[1], bh0[2], bh0[3]);
            MMA_F16(acc[0][2], a[0], bh1[0], bh1[1]);
            MMA_F16(acc[0][3], a[0], bh1[2], bh1[3]);
            MMA_F16(acc[1][2], a[1], bh1[0], bh1[1]);
            MMA_F16(acc[1][3], a[1], bh1[2], bh1[3]);
        }

        if (haveW) {
            *reinterpret_cast<uint4*>(smem + 1024u + stgW + wtoff + wdoff)      = pack8h(s0, s1);
            *reinterpret_cast<uint4*>(smem + 1024u + stgW + wtoff + wdoff + 16) = pack8h(s2, s3);
        }
        const uint32_t t = stgRd;
        stgRd = stgW; stgW = stgCp; stgCp = t;
    }

    // --- epilogue: fp32 direct stores ---
    const int g = lane >> 2;
    const int tg = lane & 3;
    #pragma unroll
    for (int mb = 0; mb < 2; mb++) {
        #pragma unroll
        for (int half = 0; half < 2; half++) {
            const int r = warpM * 32 + mb * 16 + g + half * 8;
            const int s = sSlot[r];
            if (s < 0) continue;
            #pragma unroll
            for (int nb = 0; nb < 4; nb++) {
                float2 v;
                v.x = acc[mb][nb][half * 2];
                v.y = acc[mb][nb][half * 2 + 1];
                const size_t o = (size_t)s * ND + (nBase + warpN * 32 + nb * 8 + tg * 2);
                *reinterpret_cast<float2*>(out + o) = v;
            }
        }
    }
}

// ---------------------------------------------------------------------------
// Launch. Inputs (metadata order): x, w1, w2, w3, expert_indices.
// ---------------------------------------------------------------------------
extern "C" void kernel_launch(void* const* d_in, const int* in_sizes, int n_in,
                              void* d_out, int out_size) {
    const float* x  = (const float*)d_in[0];
    const float* w1 = (const float*)d_in[1];
    const float* w2 = (const float*)d_in[2];
    const float* w3 = (const float*)d_in[3];
    const int*   idx = (const int*)d_in[4];
    float* out = (float*)d_out;

    cudaFuncSetAttribute(gemm1_tc, cudaFuncAttributeMaxDynamicSharedMemorySize, SMEM1_BYTES);
    cudaFuncSetAttribute(gemm2_tc, cudaFuncAttributeMaxDynamicSharedMemorySize, SMEM2_BYTES);

    __half* x16;
    cudaGetSymbolAddress((void**)&x16, g_x16);

    detect_and_zero_kernel<<<1, 256>>>(idx);
    route_kernel<<<NSLOT / 256, 256>>>(idx);

    const int nX8 = NT * ND / 8;
    conv_f16_kernel<<<nX8 / 256, 256>>>(x, x16, nX8);

    gemm1_tc<<<dim3(NI / BN, NSLOT / BM, NE), 512, SMEM1_BYTES>>>(w1, w3);
    gemm2_tc<<<dim3(ND / BN, NSLOT / BM2, NE), 256, SMEM2_BYTES>>>(w2, out);
}